// round 3
// baseline (speedup 1.0000x reference)
#include <cuda_runtime.h>
#include <math.h>

#define N_NODES 50000
#define DIM     128
#define E_MAX   1600000
#define NODE_BLOCKS 6250   // (N_NODES*32)/256 exactly

// ---- static device scratch (no allocation allowed) ----
__device__ float g_bufA[N_NODES * DIM];          // 25.6 MB
__device__ float g_bufB[N_NODES * DIM];          // 25.6 MB
__device__ int   g_cnt[N_NODES];
__device__ int   g_rowstart[N_NODES + 1];
__device__ int   g_fill[N_NODES];
__device__ int2  g_edge[E_MAX];                  // (col, val-bits) 12.8 MB

// ---------------------------------------------------------------------------
// Fused: logmap0 (blocks [0, NODE_BLOCKS)) + row histogram (remaining blocks).
// Independent work, overlapped in one launch.
// ---------------------------------------------------------------------------
__global__ void logmap_hist_kernel(const float* __restrict__ x, float* __restrict__ h,
                                   const int* __restrict__ rows, int E) {
    if (blockIdx.x < NODE_BLOCKS) {
        int idx  = blockIdx.x * blockDim.x + threadIdx.x;
        int node = idx >> 5;
        int lane = idx & 31;

        float4 a = reinterpret_cast<const float4*>(x + (size_t)node * DIM)[lane];
        float sq = a.x * a.x + a.y * a.y + a.z * a.z + a.w * a.w;
        if (lane == 0) sq -= a.x * a.x;
#pragma unroll
        for (int o = 16; o; o >>= 1) sq += __shfl_xor_sync(0xffffffffu, sq, o);

        float x0    = __shfl_sync(0xffffffffu, a.x, 0);
        float ynorm = fmaxf(sqrtf(sq), 1e-15f);
        float theta = fmaxf(x0, 1.0f + 1e-5f);
        float scale = acoshf(theta) / ynorm;

        float4 o4;
        o4.x = a.x * scale; o4.y = a.y * scale; o4.z = a.z * scale; o4.w = a.w * scale;
        if (lane == 0) o4.x = 0.0f;
        reinterpret_cast<float4*>(h + (size_t)node * DIM)[lane] = o4;
    } else {
        int e = (blockIdx.x - NODE_BLOCKS) * blockDim.x + threadIdx.x;
        if (e < E) atomicAdd(&g_cnt[rows[e]], 1);
    }
}

// ---------------------------------------------------------------------------
// Exclusive scan of counts (single block, sequential 1024-tiles with carry).
// Also writes g_fill[i] = exclusive prefix (removes the separate memcpy).
// ---------------------------------------------------------------------------
__global__ void scan_kernel(int n) {
    __shared__ int warpsum[32];
    __shared__ int carry;
    int tid  = threadIdx.x;
    int lane = tid & 31;
    int wid  = tid >> 5;
    if (tid == 0) { carry = 0; g_rowstart[0] = 0; }
    __syncthreads();

    for (int base = 0; base < n; base += 1024) {
        int i = base + tid;
        int v = (i < n) ? g_cnt[i] : 0;
        int s = v;
#pragma unroll
        for (int o = 1; o < 32; o <<= 1) {
            int t = __shfl_up_sync(0xffffffffu, s, o);
            if (lane >= o) s += t;
        }
        if (lane == 31) warpsum[wid] = s;
        __syncthreads();
        if (wid == 0) {
            int w = warpsum[lane];
#pragma unroll
            for (int o = 1; o < 32; o <<= 1) {
                int t = __shfl_up_sync(0xffffffffu, w, o);
                if (lane >= o) w += t;
            }
            warpsum[lane] = w;
        }
        __syncthreads();
        int off  = (wid > 0) ? warpsum[wid - 1] : 0;
        int incl = carry + off + s;
        if (i < n) {
            g_rowstart[i + 1] = incl;
            g_fill[i]         = incl - v;   // exclusive prefix
        }
        __syncthreads();
        if (tid == 1023) carry += warpsum[31];
        __syncthreads();
    }
}

// ---------------------------------------------------------------------------
// Permute (cols, vals) into row-sorted order as packed int2.
// ---------------------------------------------------------------------------
__global__ void scatter_kernel(const int* __restrict__ rows, const int* __restrict__ cols,
                               const float* __restrict__ vals, int E) {
    int e = blockIdx.x * blockDim.x + threadIdx.x;
    if (e >= E) return;
    int pos = atomicAdd(&g_fill[rows[e]], 1);
    g_edge[pos] = make_int2(cols[e], __float_as_int(vals[e]));
}

// ---------------------------------------------------------------------------
// SpMM core: one warp per row, lane = one float4 chunk. 32-edge groups loaded
// coalesced as int2; broadcast via shfl. Gathers pipelined 8-deep for MLP.
// ---------------------------------------------------------------------------
__device__ __forceinline__ float4 spmm_row(const float* __restrict__ hin,
                                           int row, int lane) {
    int s = g_rowstart[row];
    int e = g_rowstart[row + 1];
    float4 acc = make_float4(0.f, 0.f, 0.f, 0.f);

    int base = s;
    for (; base + 32 <= e; base += 32) {
        int2 ev = g_edge[base + lane];
#pragma unroll
        for (int c8 = 0; c8 < 32; c8 += 8) {
            float4 a[8];
            float  vv[8];
#pragma unroll
            for (int k = 0; k < 8; k++) {
                int ck = __shfl_sync(0xffffffffu, ev.x, c8 + k);
                vv[k]  = __int_as_float(__shfl_sync(0xffffffffu, ev.y, c8 + k));
                a[k]   = __ldcg(reinterpret_cast<const float4*>(hin + (size_t)ck * DIM) + lane);
            }
#pragma unroll
            for (int k = 0; k < 8; k++) {
                acc.x = fmaf(vv[k], a[k].x, acc.x);
                acc.y = fmaf(vv[k], a[k].y, acc.y);
                acc.z = fmaf(vv[k], a[k].z, acc.z);
                acc.w = fmaf(vv[k], a[k].w, acc.w);
            }
        }
    }
    if (base < e) {
        int cnt = e - base;
        int j   = base + lane;
        int2 ev = (lane < cnt) ? g_edge[j] : make_int2(0, 0);
        for (int k = 0; k < cnt; k++) {
            int   ck = __shfl_sync(0xffffffffu, ev.x, k);
            float vk = __int_as_float(__shfl_sync(0xffffffffu, ev.y, k));
            float4 a = __ldcg(reinterpret_cast<const float4*>(hin + (size_t)ck * DIM) + lane);
            acc.x = fmaf(vk, a.x, acc.x);
            acc.y = fmaf(vk, a.y, acc.y);
            acc.z = fmaf(vk, a.z, acc.z);
            acc.w = fmaf(vk, a.w, acc.w);
        }
    }
    return acc;
}

__global__ void spmm_csr_kernel(const float* __restrict__ hin, float* __restrict__ hout) {
    int gid  = blockIdx.x * blockDim.x + threadIdx.x;
    int row  = gid >> 5;
    int lane = gid & 31;
    if (row >= N_NODES) return;
    float4 acc = spmm_row(hin, row, lane);
    reinterpret_cast<float4*>(hout + (size_t)row * DIM)[lane] = acc;
}

// ---------------------------------------------------------------------------
// Last SpMM fused with expmap0+proj: warp holds the whole row in registers.
// ---------------------------------------------------------------------------
__global__ void spmm_expproj_kernel(const float* __restrict__ hin, float* __restrict__ out) {
    int gid  = blockIdx.x * blockDim.x + threadIdx.x;
    int row  = gid >> 5;
    int lane = gid & 31;
    if (row >= N_NODES) return;
    float4 acc = spmm_row(hin, row, lane);

    float sq = acc.x * acc.x + acc.y * acc.y + acc.z * acc.z + acc.w * acc.w;
    if (lane == 0) sq -= acc.x * acc.x;   // col 0 is exactly 0 anyway
#pragma unroll
    for (int o = 16; o; o >>= 1) sq += __shfl_xor_sync(0xffffffffu, sq, o);

    float vn = fmaxf(sqrtf(sq), 1e-15f);
    float sh = sinhf(vn);
    float sc = sh / vn;

    float4 o4;
    o4.x = acc.x * sc; o4.y = acc.y * sc; o4.z = acc.z * sc; o4.w = acc.w * sc;
    if (lane == 0) o4.x = sqrtf(fmaxf(1.0f + sh * sh, 1e-5f));   // cosh(vn)
    reinterpret_cast<float4*>(out + (size_t)row * DIM)[lane] = o4;
}

// ---------------------------------------------------------------------------
extern "C" void kernel_launch(void* const* d_in, const int* in_sizes, int n_in,
                              void* d_out, int out_size) {
    const float* x    = (const float*)d_in[0];
    const int*   rows = (const int*)  d_in[1];
    const int*   cols = (const int*)  d_in[2];
    const float* vals = (const float*)d_in[3];
    const int    E    = in_sizes[1];
    float*       out  = (float*)d_out;

    float *bufA, *bufB;
    int *cnt;
    cudaGetSymbolAddress((void**)&bufA, g_bufA);
    cudaGetSymbolAddress((void**)&bufB, g_bufB);
    cudaGetSymbolAddress((void**)&cnt,  g_cnt);

    int edgeBlocks = (E + 255) / 256;

    cudaMemsetAsync(cnt, 0, N_NODES * sizeof(int));
    logmap_hist_kernel<<<NODE_BLOCKS + edgeBlocks, 256>>>(x, bufA, rows, E);
    scan_kernel<<<1, 1024>>>(N_NODES);
    scatter_kernel<<<edgeBlocks, 256>>>(rows, cols, vals, E);

    spmm_csr_kernel<<<NODE_BLOCKS, 256>>>(bufA, bufB);
    spmm_csr_kernel<<<NODE_BLOCKS, 256>>>(bufB, bufA);
    spmm_expproj_kernel<<<NODE_BLOCKS, 256>>>(bufA, out);
}

// round 4
// speedup vs baseline: 1.3736x; 1.3736x over previous
#include <cuda_runtime.h>
#include <math.h>

#define N_NODES 50000
#define DIM     128
#define E_MAX   1600000
#define NODE_BLOCKS 6250        // (N_NODES*32)/256 exactly
#define SCAN_BLOCKS 49          // 49*1024 = 50176 >= 50000

// ---- static device scratch (no allocation allowed) ----
__device__ float g_bufA[N_NODES * DIM];          // 25.6 MB
__device__ float g_bufB[N_NODES * DIM];          // 25.6 MB
__device__ int   g_cnt[N_NODES];
__device__ int   g_rowstart[N_NODES + 1];
__device__ int   g_fill[N_NODES];
__device__ int   g_bsum[SCAN_BLOCKS];
__device__ int   g_boff[SCAN_BLOCKS];
__device__ int2  g_edge[E_MAX];                  // (col, val-bits) 12.8 MB

// ---------------------------------------------------------------------------
// Fused: logmap0 (blocks [0, NODE_BLOCKS)) + row histogram (remaining blocks).
// ---------------------------------------------------------------------------
__global__ void logmap_hist_kernel(const float* __restrict__ x, float* __restrict__ h,
                                   const int* __restrict__ rows, int E) {
    if (blockIdx.x < NODE_BLOCKS) {
        int idx  = blockIdx.x * blockDim.x + threadIdx.x;
        int node = idx >> 5;
        int lane = idx & 31;

        float4 a = reinterpret_cast<const float4*>(x + (size_t)node * DIM)[lane];
        float sq = a.x * a.x + a.y * a.y + a.z * a.z + a.w * a.w;
        if (lane == 0) sq -= a.x * a.x;
#pragma unroll
        for (int o = 16; o; o >>= 1) sq += __shfl_xor_sync(0xffffffffu, sq, o);

        float x0    = __shfl_sync(0xffffffffu, a.x, 0);
        float ynorm = fmaxf(sqrtf(sq), 1e-15f);
        float theta = fmaxf(x0, 1.0f + 1e-5f);
        float scale = acoshf(theta) / ynorm;

        float4 o4;
        o4.x = a.x * scale; o4.y = a.y * scale; o4.z = a.z * scale; o4.w = a.w * scale;
        if (lane == 0) o4.x = 0.0f;
        reinterpret_cast<float4*>(h + (size_t)node * DIM)[lane] = o4;
    } else {
        int e = (blockIdx.x - NODE_BLOCKS) * blockDim.x + threadIdx.x;
        if (e < E) atomicAdd(&g_cnt[rows[e]], 1);
    }
}

// ---------------------------------------------------------------------------
// Two-level exclusive scan of g_cnt (parallel across SCAN_BLOCKS blocks).
// Phase 1: per-block inclusive scan; writes local rowstart/fill + block sums.
// ---------------------------------------------------------------------------
__global__ void scan_partial_kernel(int n) {
    __shared__ int warpsum[32];
    int tid  = threadIdx.x;
    int lane = tid & 31;
    int wid  = tid >> 5;
    int i = blockIdx.x * 1024 + tid;

    int v = (i < n) ? g_cnt[i] : 0;
    int s = v;
#pragma unroll
    for (int o = 1; o < 32; o <<= 1) {
        int t = __shfl_up_sync(0xffffffffu, s, o);
        if (lane >= o) s += t;
    }
    if (lane == 31) warpsum[wid] = s;
    __syncthreads();
    if (wid == 0) {
        int w = warpsum[lane];
#pragma unroll
        for (int o = 1; o < 32; o <<= 1) {
            int t = __shfl_up_sync(0xffffffffu, w, o);
            if (lane >= o) w += t;
        }
        warpsum[lane] = w;
    }
    __syncthreads();
    int off  = (wid > 0) ? warpsum[wid - 1] : 0;
    int incl = off + s;
    if (i < n) {
        g_rowstart[i + 1] = incl;      // local inclusive (offset added in fixup)
        g_fill[i]         = incl - v;  // local exclusive
    }
    if (tid == 1023) g_bsum[blockIdx.x] = incl;   // block total
}

// Phase 2: exclusive scan of block sums (1 block, 64 threads, smem Hillis-Steele).
__global__ void scan_bsums_kernel(int nb) {
    __shared__ int sm[64];
    int tid = threadIdx.x;
    sm[tid] = (tid < nb) ? g_bsum[tid] : 0;
    __syncthreads();
#pragma unroll
    for (int o = 1; o < 64; o <<= 1) {
        int t = (tid >= o) ? sm[tid - o] : 0;
        __syncthreads();
        sm[tid] += t;
        __syncthreads();
    }
    if (tid < nb) g_boff[tid] = (tid > 0) ? sm[tid - 1] : 0;
}

// Phase 3: add block offsets.
__global__ void scan_fixup_kernel(int n) {
    int off = g_boff[blockIdx.x];
    int i   = blockIdx.x * 1024 + threadIdx.x;
    if (i < n) {
        g_rowstart[i + 1] += off;
        g_fill[i]         += off;
    }
    if (i == 0) g_rowstart[0] = 0;
}

// ---------------------------------------------------------------------------
// Permute (cols, vals) into row-sorted order as packed int2.
// ---------------------------------------------------------------------------
__global__ void scatter_kernel(const int* __restrict__ rows, const int* __restrict__ cols,
                               const float* __restrict__ vals, int E) {
    int e = blockIdx.x * blockDim.x + threadIdx.x;
    if (e >= E) return;
    int pos = atomicAdd(&g_fill[rows[e]], 1);
    g_edge[pos] = make_int2(cols[e], __float_as_int(vals[e]));
}

// ---------------------------------------------------------------------------
// SpMM core: one warp per row, lane = one float4 chunk. Depth-2 load pipeline,
// registers capped (launch_bounds) so occupancy stays at max.
// ---------------------------------------------------------------------------
__device__ __forceinline__ float4 spmm_row(const float* __restrict__ hin,
                                           int row, int lane) {
    int s = g_rowstart[row];
    int e = g_rowstart[row + 1];
    float4 acc = make_float4(0.f, 0.f, 0.f, 0.f);

    int base = s;
    for (; base + 32 <= e; base += 32) {
        int2 ev = g_edge[base + lane];
#pragma unroll
        for (int k = 0; k < 32; k += 2) {
            int   c0 = __shfl_sync(0xffffffffu, ev.x, k);
            int   c1 = __shfl_sync(0xffffffffu, ev.x, k + 1);
            float v0 = __int_as_float(__shfl_sync(0xffffffffu, ev.y, k));
            float v1 = __int_as_float(__shfl_sync(0xffffffffu, ev.y, k + 1));
            float4 a0 = __ldcg(reinterpret_cast<const float4*>(hin + (size_t)c0 * DIM) + lane);
            float4 a1 = __ldcg(reinterpret_cast<const float4*>(hin + (size_t)c1 * DIM) + lane);
            acc.x = fmaf(v0, a0.x, acc.x);
            acc.y = fmaf(v0, a0.y, acc.y);
            acc.z = fmaf(v0, a0.z, acc.z);
            acc.w = fmaf(v0, a0.w, acc.w);
            acc.x = fmaf(v1, a1.x, acc.x);
            acc.y = fmaf(v1, a1.y, acc.y);
            acc.z = fmaf(v1, a1.z, acc.z);
            acc.w = fmaf(v1, a1.w, acc.w);
        }
    }
    if (base < e) {
        int cnt = e - base;
        int2 ev = (lane < cnt) ? g_edge[base + lane] : make_int2(0, 0);
        for (int k = 0; k < cnt; k++) {
            int   ck = __shfl_sync(0xffffffffu, ev.x, k);
            float vk = __int_as_float(__shfl_sync(0xffffffffu, ev.y, k));
            float4 a = __ldcg(reinterpret_cast<const float4*>(hin + (size_t)ck * DIM) + lane);
            acc.x = fmaf(vk, a.x, acc.x);
            acc.y = fmaf(vk, a.y, acc.y);
            acc.z = fmaf(vk, a.z, acc.z);
            acc.w = fmaf(vk, a.w, acc.w);
        }
    }
    return acc;
}

__global__ void __launch_bounds__(256, 8)
spmm_csr_kernel(const float* __restrict__ hin, float* __restrict__ hout) {
    int gid  = blockIdx.x * blockDim.x + threadIdx.x;
    int row  = gid >> 5;
    int lane = gid & 31;
    if (row >= N_NODES) return;
    float4 acc = spmm_row(hin, row, lane);
    reinterpret_cast<float4*>(hout + (size_t)row * DIM)[lane] = acc;
}

// ---------------------------------------------------------------------------
// Last SpMM fused with expmap0+proj.
// ---------------------------------------------------------------------------
__global__ void __launch_bounds__(256, 8)
spmm_expproj_kernel(const float* __restrict__ hin, float* __restrict__ out) {
    int gid  = blockIdx.x * blockDim.x + threadIdx.x;
    int row  = gid >> 5;
    int lane = gid & 31;
    if (row >= N_NODES) return;
    float4 acc = spmm_row(hin, row, lane);

    float sq = acc.x * acc.x + acc.y * acc.y + acc.z * acc.z + acc.w * acc.w;
    if (lane == 0) sq -= acc.x * acc.x;   // col 0 is exactly 0 anyway
#pragma unroll
    for (int o = 16; o; o >>= 1) sq += __shfl_xor_sync(0xffffffffu, sq, o);

    float vn = fmaxf(sqrtf(sq), 1e-15f);
    float sh = sinhf(vn);
    float sc = sh / vn;

    float4 o4;
    o4.x = acc.x * sc; o4.y = acc.y * sc; o4.z = acc.z * sc; o4.w = acc.w * sc;
    if (lane == 0) o4.x = sqrtf(fmaxf(1.0f + sh * sh, 1e-5f));   // cosh(vn)
    reinterpret_cast<float4*>(out + (size_t)row * DIM)[lane] = o4;
}

// ---------------------------------------------------------------------------
extern "C" void kernel_launch(void* const* d_in, const int* in_sizes, int n_in,
                              void* d_out, int out_size) {
    const float* x    = (const float*)d_in[0];
    const int*   rows = (const int*)  d_in[1];
    const int*   cols = (const int*)  d_in[2];
    const float* vals = (const float*)d_in[3];
    const int    E    = in_sizes[1];
    float*       out  = (float*)d_out;

    float *bufA, *bufB;
    int *cnt;
    cudaGetSymbolAddress((void**)&bufA, g_bufA);
    cudaGetSymbolAddress((void**)&bufB, g_bufB);
    cudaGetSymbolAddress((void**)&cnt,  g_cnt);

    int edgeBlocks = (E + 255) / 256;

    // ---- CSR build ----
    cudaMemsetAsync(cnt, 0, N_NODES * sizeof(int));
    logmap_hist_kernel<<<NODE_BLOCKS + edgeBlocks, 256>>>(x, bufA, rows, E);
    scan_partial_kernel<<<SCAN_BLOCKS, 1024>>>(N_NODES);
    scan_bsums_kernel<<<1, 64>>>(SCAN_BLOCKS);
    scan_fixup_kernel<<<SCAN_BLOCKS, 1024>>>(N_NODES);
    scatter_kernel<<<edgeBlocks, 256>>>(rows, cols, vals, E);

    // ---- 3 GCN layers (last fused with expmap0+proj) ----
    spmm_csr_kernel<<<NODE_BLOCKS, 256>>>(bufA, bufB);
    spmm_csr_kernel<<<NODE_BLOCKS, 256>>>(bufB, bufA);
    spmm_expproj_kernel<<<NODE_BLOCKS, 256>>>(bufA, out);
}

// round 5
// speedup vs baseline: 1.8052x; 1.3142x over previous
#include <cuda_runtime.h>
#include <cuda_fp16.h>
#include <math.h>

#define N_NODES 50000
#define DIM     128
#define E_MAX   1600000
#define NODE_BLOCKS 6250        // (N_NODES*32)/256 exactly
#define SCAN_BLOCKS 49          // 49*1024 = 50176 >= 50000

// ---- static device scratch (no allocation allowed) ----
__device__ __half g_hA[N_NODES * DIM];           // 12.8 MB fp16 features
__device__ __half g_hB[N_NODES * DIM];           // 12.8 MB fp16 features
__device__ int    g_cnt[N_NODES];
__device__ int    g_rowstart[N_NODES + 1];
__device__ int    g_fill[N_NODES];
__device__ int    g_bsum[SCAN_BLOCKS];
__device__ int    g_boff[SCAN_BLOCKS];
__device__ int2   g_edge[E_MAX];                 // (col, val-bits) 12.8 MB

// ---------------------------------------------------------------------------
// Fused: logmap0 (blocks [0, NODE_BLOCKS)) + row histogram (remaining blocks).
// logmap output stored fp16.
// ---------------------------------------------------------------------------
__global__ void logmap_hist_kernel(const float* __restrict__ x, __half* __restrict__ h,
                                   const int* __restrict__ rows, int E) {
    if (blockIdx.x < NODE_BLOCKS) {
        int idx  = blockIdx.x * blockDim.x + threadIdx.x;
        int node = idx >> 5;
        int lane = idx & 31;

        float4 a = reinterpret_cast<const float4*>(x + (size_t)node * DIM)[lane];
        float sq = a.x * a.x + a.y * a.y + a.z * a.z + a.w * a.w;
        if (lane == 0) sq -= a.x * a.x;
#pragma unroll
        for (int o = 16; o; o >>= 1) sq += __shfl_xor_sync(0xffffffffu, sq, o);

        float x0    = __shfl_sync(0xffffffffu, a.x, 0);
        float ynorm = fmaxf(sqrtf(sq), 1e-15f);
        float theta = fmaxf(x0, 1.0f + 1e-5f);
        float scale = acoshf(theta) / ynorm;

        float4 o4;
        o4.x = a.x * scale; o4.y = a.y * scale; o4.z = a.z * scale; o4.w = a.w * scale;
        if (lane == 0) o4.x = 0.0f;

        uint2 packed;
        __half2 p0 = __floats2half2_rn(o4.x, o4.y);
        __half2 p1 = __floats2half2_rn(o4.z, o4.w);
        packed.x = *reinterpret_cast<unsigned*>(&p0);
        packed.y = *reinterpret_cast<unsigned*>(&p1);
        reinterpret_cast<uint2*>(h + (size_t)node * DIM)[lane] = packed;
    } else {
        int e = (blockIdx.x - NODE_BLOCKS) * blockDim.x + threadIdx.x;
        if (e < E) atomicAdd(&g_cnt[rows[e]], 1);
    }
}

// ---------------------------------------------------------------------------
// Two-level exclusive scan of g_cnt.
// ---------------------------------------------------------------------------
__global__ void scan_partial_kernel(int n) {
    __shared__ int warpsum[32];
    int tid  = threadIdx.x;
    int lane = tid & 31;
    int wid  = tid >> 5;
    int i = blockIdx.x * 1024 + tid;

    int v = (i < n) ? g_cnt[i] : 0;
    int s = v;
#pragma unroll
    for (int o = 1; o < 32; o <<= 1) {
        int t = __shfl_up_sync(0xffffffffu, s, o);
        if (lane >= o) s += t;
    }
    if (lane == 31) warpsum[wid] = s;
    __syncthreads();
    if (wid == 0) {
        int w = warpsum[lane];
#pragma unroll
        for (int o = 1; o < 32; o <<= 1) {
            int t = __shfl_up_sync(0xffffffffu, w, o);
            if (lane >= o) w += t;
        }
        warpsum[lane] = w;
    }
    __syncthreads();
    int off  = (wid > 0) ? warpsum[wid - 1] : 0;
    int incl = off + s;
    if (i < n) {
        g_rowstart[i + 1] = incl;
        g_fill[i]         = incl - v;
    }
    if (tid == 1023) g_bsum[blockIdx.x] = incl;
}

__global__ void scan_bsums_kernel(int nb) {
    __shared__ int sm[64];
    int tid = threadIdx.x;
    sm[tid] = (tid < nb) ? g_bsum[tid] : 0;
    __syncthreads();
#pragma unroll
    for (int o = 1; o < 64; o <<= 1) {
        int t = (tid >= o) ? sm[tid - o] : 0;
        __syncthreads();
        sm[tid] += t;
        __syncthreads();
    }
    if (tid < nb) g_boff[tid] = (tid > 0) ? sm[tid - 1] : 0;
}

__global__ void scan_fixup_kernel(int n) {
    int off = g_boff[blockIdx.x];
    int i   = blockIdx.x * 1024 + threadIdx.x;
    if (i < n) {
        g_rowstart[i + 1] += off;
        g_fill[i]         += off;
    }
    if (i == 0) g_rowstart[0] = 0;
}

// ---------------------------------------------------------------------------
// Permute (cols, vals) into row-sorted order as packed int2.
// ---------------------------------------------------------------------------
__global__ void scatter_kernel(const int* __restrict__ rows, const int* __restrict__ cols,
                               const float* __restrict__ vals, int E) {
    int e = blockIdx.x * blockDim.x + threadIdx.x;
    if (e >= E) return;
    int pos = atomicAdd(&g_fill[rows[e]], 1);
    g_edge[pos] = make_int2(cols[e], __float_as_int(vals[e]));
}

// ---------------------------------------------------------------------------
// SpMM core on fp16 features, fp32 accumulate. One warp per row, lane owns
// 4 features (one uint2 = 2x half2 per gathered row). Depth-2 load pipeline.
// ---------------------------------------------------------------------------
__device__ __forceinline__ float4 spmm_row_h(const __half* __restrict__ hin,
                                             int row, int lane) {
    int s = g_rowstart[row];
    int e = g_rowstart[row + 1];
    float4 acc = make_float4(0.f, 0.f, 0.f, 0.f);

    int base = s;
    for (; base + 32 <= e; base += 32) {
        int2 ev = g_edge[base + lane];
#pragma unroll
        for (int k = 0; k < 32; k += 2) {
            int   c0 = __shfl_sync(0xffffffffu, ev.x, k);
            int   c1 = __shfl_sync(0xffffffffu, ev.x, k + 1);
            float v0 = __int_as_float(__shfl_sync(0xffffffffu, ev.y, k));
            float v1 = __int_as_float(__shfl_sync(0xffffffffu, ev.y, k + 1));
            uint2 a0 = __ldcg(reinterpret_cast<const uint2*>(hin + (size_t)c0 * DIM) + lane);
            uint2 a1 = __ldcg(reinterpret_cast<const uint2*>(hin + (size_t)c1 * DIM) + lane);

            float2 f00 = __half22float2(*reinterpret_cast<__half2*>(&a0.x));
            float2 f01 = __half22float2(*reinterpret_cast<__half2*>(&a0.y));
            acc.x = fmaf(v0, f00.x, acc.x);
            acc.y = fmaf(v0, f00.y, acc.y);
            acc.z = fmaf(v0, f01.x, acc.z);
            acc.w = fmaf(v0, f01.y, acc.w);

            float2 f10 = __half22float2(*reinterpret_cast<__half2*>(&a1.x));
            float2 f11 = __half22float2(*reinterpret_cast<__half2*>(&a1.y));
            acc.x = fmaf(v1, f10.x, acc.x);
            acc.y = fmaf(v1, f10.y, acc.y);
            acc.z = fmaf(v1, f11.x, acc.z);
            acc.w = fmaf(v1, f11.y, acc.w);
        }
    }
    if (base < e) {
        int cnt = e - base;
        int2 ev = (lane < cnt) ? g_edge[base + lane] : make_int2(0, 0);
        for (int k = 0; k < cnt; k++) {
            int   ck = __shfl_sync(0xffffffffu, ev.x, k);
            float vk = __int_as_float(__shfl_sync(0xffffffffu, ev.y, k));
            uint2 a  = __ldcg(reinterpret_cast<const uint2*>(hin + (size_t)ck * DIM) + lane);
            float2 f0 = __half22float2(*reinterpret_cast<__half2*>(&a.x));
            float2 f1 = __half22float2(*reinterpret_cast<__half2*>(&a.y));
            acc.x = fmaf(vk, f0.x, acc.x);
            acc.y = fmaf(vk, f0.y, acc.y);
            acc.z = fmaf(vk, f1.x, acc.z);
            acc.w = fmaf(vk, f1.y, acc.w);
        }
    }
    return acc;
}

__global__ void __launch_bounds__(256, 8)
spmm_csr_kernel(const __half* __restrict__ hin, __half* __restrict__ hout) {
    int gid  = blockIdx.x * blockDim.x + threadIdx.x;
    int row  = gid >> 5;
    int lane = gid & 31;
    if (row >= N_NODES) return;
    float4 acc = spmm_row_h(hin, row, lane);

    uint2 packed;
    __half2 p0 = __floats2half2_rn(acc.x, acc.y);
    __half2 p1 = __floats2half2_rn(acc.z, acc.w);
    packed.x = *reinterpret_cast<unsigned*>(&p0);
    packed.y = *reinterpret_cast<unsigned*>(&p1);
    reinterpret_cast<uint2*>(hout + (size_t)row * DIM)[lane] = packed;
}

// ---------------------------------------------------------------------------
// Last SpMM fused with expmap0+proj; fp32 output (no quantization on output).
// ---------------------------------------------------------------------------
__global__ void __launch_bounds__(256, 8)
spmm_expproj_kernel(const __half* __restrict__ hin, float* __restrict__ out) {
    int gid  = blockIdx.x * blockDim.x + threadIdx.x;
    int row  = gid >> 5;
    int lane = gid & 31;
    if (row >= N_NODES) return;
    float4 acc = spmm_row_h(hin, row, lane);

    float sq = acc.x * acc.x + acc.y * acc.y + acc.z * acc.z + acc.w * acc.w;
    if (lane == 0) sq -= acc.x * acc.x;   // col 0 is exactly 0 anyway
#pragma unroll
    for (int o = 16; o; o >>= 1) sq += __shfl_xor_sync(0xffffffffu, sq, o);

    float vn = fmaxf(sqrtf(sq), 1e-15f);
    float sh = sinhf(vn);
    float sc = sh / vn;

    float4 o4;
    o4.x = acc.x * sc; o4.y = acc.y * sc; o4.z = acc.z * sc; o4.w = acc.w * sc;
    if (lane == 0) o4.x = sqrtf(fmaxf(1.0f + sh * sh, 1e-5f));   // cosh(vn)
    reinterpret_cast<float4*>(out + (size_t)row * DIM)[lane] = o4;
}

// ---------------------------------------------------------------------------
extern "C" void kernel_launch(void* const* d_in, const int* in_sizes, int n_in,
                              void* d_out, int out_size) {
    const float* x    = (const float*)d_in[0];
    const int*   rows = (const int*)  d_in[1];
    const int*   cols = (const int*)  d_in[2];
    const float* vals = (const float*)d_in[3];
    const int    E    = in_sizes[1];
    float*       out  = (float*)d_out;

    __half *hA, *hB;
    int *cnt;
    cudaGetSymbolAddress((void**)&hA,  g_hA);
    cudaGetSymbolAddress((void**)&hB,  g_hB);
    cudaGetSymbolAddress((void**)&cnt, g_cnt);

    int edgeBlocks = (E + 255) / 256;

    // ---- CSR build ----
    cudaMemsetAsync(cnt, 0, N_NODES * sizeof(int));
    logmap_hist_kernel<<<NODE_BLOCKS + edgeBlocks, 256>>>(x, hA, rows, E);
    scan_partial_kernel<<<SCAN_BLOCKS, 1024>>>(N_NODES);
    scan_bsums_kernel<<<1, 64>>>(SCAN_BLOCKS);
    scan_fixup_kernel<<<SCAN_BLOCKS, 1024>>>(N_NODES);
    scatter_kernel<<<edgeBlocks, 256>>>(rows, cols, vals, E);

    // ---- 3 GCN layers (last fused with expmap0+proj) ----
    spmm_csr_kernel<<<NODE_BLOCKS, 256>>>(hA, hB);
    spmm_csr_kernel<<<NODE_BLOCKS, 256>>>(hB, hA);
    spmm_expproj_kernel<<<NODE_BLOCKS, 256>>>(hA, out);
}